// round 1
// baseline (speedup 1.0000x reference)
#include <cuda_runtime.h>
#include <math.h>

// ---------------- scratch (device globals: allocation-free rule) -------------
__device__ float g_feat[512 * 8192];   // chain output features
__device__ float g_h1[512 * 4096];     // MLP hidden 1
__device__ float g_h2[512 * 4096];     // MLP hidden 2

// XOR-swizzled word address for a 64x64 fp32 tile stored row-major (stride 64),
// logical element (r, q). 16B-chunk index is XORed with r>>2 so that lanes
// reading different rows at the same q hit distinct banks.
__device__ __forceinline__ int sw_addr(int r, int q) {
    return (r << 6) + ((((q >> 2) ^ (r >> 2)) & 15) << 2) + (q & 3);
}

__device__ __forceinline__ float mishf(float x) {
    float sp = (x > 20.f) ? x : log1pf(expf(x));
    return x * tanhf(sp);
}

// ---------------------------------------------------------------------------
// Phase 1: complex matrix chain. One CTA per batch element.
//   cur = x[b,0]
//   for i in 0..6: tmp = W[i] @ cur ; cur = x[b,i+1] @ tmp
//   cur = W[7] @ cur ; feat = concat(u - cur) layout (p*128 + [r | 64+r])
// The running matrix is held TRANSPOSED (+swizzled) in smem so the compute
// inner loop reads both operands contiguously along q.
// ---------------------------------------------------------------------------
__global__ void __launch_bounds__(256, 2)
chain_kernel(const float* __restrict__ x_r, const float* __restrict__ x_i,
             const float* __restrict__ u_r, const float* __restrict__ u_i,
             const float* __restrict__ W_r, const float* __restrict__ W_i,
             float* __restrict__ feat)
{
    extern __shared__ float sm[];
    float* m_r = sm;             // staged left matrix, plain row-major [64][64]
    float* m_i = sm + 4096;
    float* bufA_r = sm + 8192;   // ping-pong transposed/swizzled buffers
    float* bufA_i = sm + 12288;
    float* bufB_r = sm + 16384;
    float* bufB_i = sm + 20480;

    const int tx = threadIdx.x, ty = threadIdx.y;
    const int tid = ty * 16 + tx;
    const int b = blockIdx.x;

    const float* xr = x_r + (size_t)b * 8 * 4096;
    const float* xi = x_i + (size_t)b * 8 * 4096;

    float* cur_r = bufA_r; float* cur_i = bufA_i;
    float* nxt_r = bufB_r; float* nxt_i = bufB_i;

    // stage x[b,0] transposed + swizzled: cur(logical r,q) = x0[q][r]
    for (int e = tid; e < 4096; e += 256) {
        int a = e >> 6, c = e & 63;          // x0 row a, col c
        int ao = sw_addr(c, a);
        cur_r[ao] = xr[e];
        cur_i[ao] = xi[e];
    }

    const int p0 = ty << 2;   // output row tile
    const int r0 = tx << 2;   // output col tile

    #pragma unroll 1
    for (int s = 0; s < 15; s++) {
        const float* Mr;
        const float* Mi;
        if (s & 1) { int l = (s + 1) >> 1; Mr = xr  + l * 4096; Mi = xi  + l * 4096; }
        else       { int l = s >> 1;       Mr = W_r + l * 4096; Mi = W_i + l * 4096; }

        __syncthreads();   // prev compute done (m free), prev result visible
        for (int e = tid; e < 4096; e += 256) { m_r[e] = Mr[e]; m_i[e] = Mi[e]; }
        __syncthreads();

        float accr[4][4] = {}, acci[4][4] = {};
        #pragma unroll 1
        for (int q = 0; q < 64; q += 4) {
            float mr[4][4], mi[4][4], ar[4][4], ai[4][4];
            #pragma unroll
            for (int j = 0; j < 4; j++) {
                float4 t;
                t = *(const float4*)&m_r[(p0 + j) * 64 + q];
                mr[j][0] = t.x; mr[j][1] = t.y; mr[j][2] = t.z; mr[j][3] = t.w;
                t = *(const float4*)&m_i[(p0 + j) * 64 + q];
                mi[j][0] = t.x; mi[j][1] = t.y; mi[j][2] = t.z; mi[j][3] = t.w;
                int ao = sw_addr(r0 + j, q);
                t = *(const float4*)&cur_r[ao];
                ar[j][0] = t.x; ar[j][1] = t.y; ar[j][2] = t.z; ar[j][3] = t.w;
                t = *(const float4*)&cur_i[ao];
                ai[j][0] = t.x; ai[j][1] = t.y; ai[j][2] = t.z; ai[j][3] = t.w;
            }
            #pragma unroll
            for (int jp = 0; jp < 4; jp++)
                #pragma unroll
                for (int jr = 0; jr < 4; jr++) {
                    float sr = accr[jp][jr], si = acci[jp][jr];
                    #pragma unroll
                    for (int jq = 0; jq < 4; jq++) {
                        sr = fmaf(mr[jp][jq], ar[jr][jq], sr);
                        sr = fmaf(-mi[jp][jq], ai[jr][jq], sr);
                        si = fmaf(mr[jp][jq], ai[jr][jq], si);
                        si = fmaf(mi[jp][jq], ar[jr][jq], si);
                    }
                    accr[jp][jr] = sr; acci[jp][jr] = si;
                }
        }

        // store result transposed: nxt(logical r, p) = tmp[p][r]
        #pragma unroll
        for (int jr = 0; jr < 4; jr++) {
            int ao = sw_addr(r0 + jr, p0);
            float4 vr = make_float4(accr[0][jr], accr[1][jr], accr[2][jr], accr[3][jr]);
            float4 vi = make_float4(acci[0][jr], acci[1][jr], acci[2][jr], acci[3][jr]);
            *(float4*)&nxt_r[ao] = vr;
            *(float4*)&nxt_i[ao] = vi;
        }

        float* t;
        t = cur_r; cur_r = nxt_r; nxt_r = t;
        t = cur_i; cur_i = nxt_i; nxt_i = t;
    }
    __syncthreads();

    // feat[b, p*128 + r] = (u - out).real[p][r]; +64 for imag
    const float* ur = u_r + (size_t)b * 4096;
    const float* ui = u_i + (size_t)b * 4096;
    float* fb = feat + (size_t)b * 8192;
    for (int e = tid; e < 4096; e += 256) {
        int p = e >> 6, r = e & 63;
        int ao = sw_addr(r, p);                  // cur(r,p) = out[p][r]
        fb[(p << 7) + r]      = ur[e] - cur_r[ao];
        fb[(p << 7) + 64 + r] = ui[e] - cur_i[ao];
    }
}

// ---------------------------------------------------------------------------
// Phase 2: MLP GEMM  C[512, 4096] = mish(A[512,K] @ W[4096,K]^T + bias)
// Both operands K-contiguous -> dot-product micro-kernel, no transposes.
// BM=BN=64, BK=32, 256 threads, 4x4 per thread, register prefetch.
// ---------------------------------------------------------------------------
template <int K>
__global__ void __launch_bounds__(256, 2)
mlp_gemm(const float* __restrict__ A, const float* __restrict__ Bw,
         const float* __restrict__ bias, float* __restrict__ C)
{
    __shared__ float As[64 * 32];
    __shared__ float Bs[64 * 32];

    const int tid = threadIdx.x;
    const int tx = tid & 15, ty = tid >> 4;
    const int p0 = ty << 2;       // m within tile
    const int n0 = tx << 2;       // n within tile

    const int lrow = tid >> 3;          // 0..31
    const int lcol = (tid & 7) << 2;    // 0..28 step 4

    const float* Ab = A  + (size_t)(blockIdx.y * 64) * K;
    const float* Bb = Bw + (size_t)(blockIdx.x * 64) * K;

    float acc[4][4] = {};

    // prologue prefetch
    float4 a0 = *(const float4*)&Ab[(size_t)lrow * K + lcol];
    float4 a1 = *(const float4*)&Ab[(size_t)(lrow + 32) * K + lcol];
    float4 b0 = *(const float4*)&Bb[(size_t)lrow * K + lcol];
    float4 b1 = *(const float4*)&Bb[(size_t)(lrow + 32) * K + lcol];

    const int swz = (((lcol >> 2) ^ (lrow >> 2)) & 7) << 2; // same for lrow+32

    #pragma unroll 1
    for (int kb = 0; kb < K; kb += 32) {
        *(float4*)&As[lrow * 32 + lcol]        = a0;
        *(float4*)&As[(lrow + 32) * 32 + lcol] = a1;
        *(float4*)&Bs[lrow * 32 + swz]         = b0;
        *(float4*)&Bs[(lrow + 32) * 32 + swz]  = b1;
        __syncthreads();

        if (kb + 32 < K) {
            a0 = *(const float4*)&Ab[(size_t)lrow * K + kb + 32 + lcol];
            a1 = *(const float4*)&Ab[(size_t)(lrow + 32) * K + kb + 32 + lcol];
            b0 = *(const float4*)&Bb[(size_t)lrow * K + kb + 32 + lcol];
            b1 = *(const float4*)&Bb[(size_t)(lrow + 32) * K + kb + 32 + lcol];
        }

        #pragma unroll
        for (int kk = 0; kk < 32; kk += 4) {
            float av[4][4], bv[4][4];
            #pragma unroll
            for (int j = 0; j < 4; j++) {
                float4 t = *(const float4*)&As[(p0 + j) * 32 + kk];
                av[j][0] = t.x; av[j][1] = t.y; av[j][2] = t.z; av[j][3] = t.w;
                int n = n0 + j;
                t = *(const float4*)&Bs[n * 32 + ((((kk >> 2) ^ (n >> 2)) & 7) << 2)];
                bv[j][0] = t.x; bv[j][1] = t.y; bv[j][2] = t.z; bv[j][3] = t.w;
            }
            #pragma unroll
            for (int im = 0; im < 4; im++)
                #pragma unroll
                for (int in = 0; in < 4; in++) {
                    float s = acc[im][in];
                    s = fmaf(av[im][0], bv[in][0], s);
                    s = fmaf(av[im][1], bv[in][1], s);
                    s = fmaf(av[im][2], bv[in][2], s);
                    s = fmaf(av[im][3], bv[in][3], s);
                    acc[im][in] = s;
                }
        }
        __syncthreads();
    }

    const int gn = blockIdx.x * 64 + n0;
    const float bv0 = bias[gn], bv1 = bias[gn + 1], bv2 = bias[gn + 2], bv3 = bias[gn + 3];
    #pragma unroll
    for (int im = 0; im < 4; im++) {
        int gm = blockIdx.y * 64 + p0 + im;
        float4 o;
        o.x = mishf(acc[im][0] + bv0);
        o.y = mishf(acc[im][1] + bv1);
        o.z = mishf(acc[im][2] + bv2);
        o.w = mishf(acc[im][3] + bv3);
        *(float4*)&C[(size_t)gm * 4096 + gn] = o;
    }
}

// ---------------------------------------------------------------------------
// Phase 3: out[b] = h2[b,:] . w3 + b3
// ---------------------------------------------------------------------------
__global__ void final_kernel(const float* __restrict__ H,
                             const float* __restrict__ w3,
                             const float* __restrict__ b3,
                             float* __restrict__ out)
{
    const int b = blockIdx.x;
    const float* h = H + (size_t)b * 4096;
    float s = 0.f;
    for (int i = threadIdx.x; i < 4096; i += 256)
        s = fmaf(h[i], w3[i], s);
    #pragma unroll
    for (int o = 16; o > 0; o >>= 1)
        s += __shfl_down_sync(0xffffffffu, s, o);
    __shared__ float red[8];
    if ((threadIdx.x & 31) == 0) red[threadIdx.x >> 5] = s;
    __syncthreads();
    if (threadIdx.x == 0) {
        float t = 0.f;
        #pragma unroll
        for (int i = 0; i < 8; i++) t += red[i];
        out[b] = t + b3[0];
    }
}

// ---------------------------------------------------------------------------
extern "C" void kernel_launch(void* const* d_in, const int* in_sizes, int n_in,
                              void* d_out, int out_size)
{
    const float* x_r = (const float*)d_in[0];
    const float* x_i = (const float*)d_in[1];
    const float* u_r = (const float*)d_in[2];
    const float* u_i = (const float*)d_in[3];
    const float* W_r = (const float*)d_in[4];
    const float* W_i = (const float*)d_in[5];
    const float* w1  = (const float*)d_in[6];
    const float* b1  = (const float*)d_in[7];
    const float* w2  = (const float*)d_in[8];
    const float* b2  = (const float*)d_in[9];
    const float* w3  = (const float*)d_in[10];
    const float* b3  = (const float*)d_in[11];
    float* out = (float*)d_out;

    float *feat, *h1, *h2;
    cudaGetSymbolAddress((void**)&feat, g_feat);
    cudaGetSymbolAddress((void**)&h1, g_h1);
    cudaGetSymbolAddress((void**)&h2, g_h2);

    cudaFuncSetAttribute((const void*)chain_kernel,
                         cudaFuncAttributeMaxDynamicSharedMemorySize, 98304);

    chain_kernel<<<512, dim3(16, 16), 98304>>>(x_r, x_i, u_r, u_i, W_r, W_i, feat);
    mlp_gemm<8192><<<dim3(64, 8), 256>>>(feat, w1, b1, h1);
    mlp_gemm<4096><<<dim3(64, 8), 256>>>(h1, w2, b2, h2);
    final_kernel<<<512, 256>>>(h2, w3, b3, out);
}

// round 2
// speedup vs baseline: 2.8671x; 2.8671x over previous
#include <cuda_runtime.h>
#include <cuda_bf16.h>
#include <math.h>

// ---------------- scratch (device globals: allocation-free rule) -------------
__device__ float g_feat[512 * 8192];   // chain output features
__device__ float g_h1[512 * 4096];     // MLP hidden 1
__device__ float g_h2[512 * 4096];     // MLP hidden 2

// XOR-swizzled word address for a 64x64 fp32 tile stored row-major (stride 64)
__device__ __forceinline__ int sw_addr(int r, int q) {
    return (r << 6) + ((((q >> 2) ^ (r >> 2)) & 15) << 2) + (q & 3);
}

__device__ __forceinline__ float mishf(float x) {
    float sp = (x > 20.f) ? x : log1pf(expf(x));
    return x * tanhf(sp);
}

// ---------------------------------------------------------------------------
// Phase 1: complex matrix chain (unchanged from R1 — FFMA, next round's target)
// ---------------------------------------------------------------------------
__global__ void __launch_bounds__(256, 2)
chain_kernel(const float* __restrict__ x_r, const float* __restrict__ x_i,
             const float* __restrict__ u_r, const float* __restrict__ u_i,
             const float* __restrict__ W_r, const float* __restrict__ W_i,
             float* __restrict__ feat)
{
    extern __shared__ float sm[];
    float* m_r = sm;
    float* m_i = sm + 4096;
    float* bufA_r = sm + 8192;
    float* bufA_i = sm + 12288;
    float* bufB_r = sm + 16384;
    float* bufB_i = sm + 20480;

    const int tx = threadIdx.x, ty = threadIdx.y;
    const int tid = ty * 16 + tx;
    const int b = blockIdx.x;

    const float* xr = x_r + (size_t)b * 8 * 4096;
    const float* xi = x_i + (size_t)b * 8 * 4096;

    float* cur_r = bufA_r; float* cur_i = bufA_i;
    float* nxt_r = bufB_r; float* nxt_i = bufB_i;

    for (int e = tid; e < 4096; e += 256) {
        int a = e >> 6, c = e & 63;
        int ao = sw_addr(c, a);
        cur_r[ao] = xr[e];
        cur_i[ao] = xi[e];
    }

    const int p0 = ty << 2;
    const int r0 = tx << 2;

    #pragma unroll 1
    for (int s = 0; s < 15; s++) {
        const float* Mr;
        const float* Mi;
        if (s & 1) { int l = (s + 1) >> 1; Mr = xr  + l * 4096; Mi = xi  + l * 4096; }
        else       { int l = s >> 1;       Mr = W_r + l * 4096; Mi = W_i + l * 4096; }

        __syncthreads();
        for (int e = tid; e < 4096; e += 256) { m_r[e] = Mr[e]; m_i[e] = Mi[e]; }
        __syncthreads();

        float accr[4][4] = {}, acci[4][4] = {};
        #pragma unroll 1
        for (int q = 0; q < 64; q += 4) {
            float mr[4][4], mi[4][4], ar[4][4], ai[4][4];
            #pragma unroll
            for (int j = 0; j < 4; j++) {
                float4 t;
                t = *(const float4*)&m_r[(p0 + j) * 64 + q];
                mr[j][0] = t.x; mr[j][1] = t.y; mr[j][2] = t.z; mr[j][3] = t.w;
                t = *(const float4*)&m_i[(p0 + j) * 64 + q];
                mi[j][0] = t.x; mi[j][1] = t.y; mi[j][2] = t.z; mi[j][3] = t.w;
                int ao = sw_addr(r0 + j, q);
                t = *(const float4*)&cur_r[ao];
                ar[j][0] = t.x; ar[j][1] = t.y; ar[j][2] = t.z; ar[j][3] = t.w;
                t = *(const float4*)&cur_i[ao];
                ai[j][0] = t.x; ai[j][1] = t.y; ai[j][2] = t.z; ai[j][3] = t.w;
            }
            #pragma unroll
            for (int jp = 0; jp < 4; jp++)
                #pragma unroll
                for (int jr = 0; jr < 4; jr++) {
                    float sr = accr[jp][jr], si = acci[jp][jr];
                    #pragma unroll
                    for (int jq = 0; jq < 4; jq++) {
                        sr = fmaf(mr[jp][jq], ar[jr][jq], sr);
                        sr = fmaf(-mi[jp][jq], ai[jr][jq], sr);
                        si = fmaf(mr[jp][jq], ai[jr][jq], si);
                        si = fmaf(mi[jp][jq], ar[jr][jq], si);
                    }
                    accr[jp][jr] = sr; acci[jp][jr] = si;
                }
        }

        #pragma unroll
        for (int jr = 0; jr < 4; jr++) {
            int ao = sw_addr(r0 + jr, p0);
            float4 vr = make_float4(accr[0][jr], accr[1][jr], accr[2][jr], accr[3][jr]);
            float4 vi = make_float4(acci[0][jr], acci[1][jr], acci[2][jr], acci[3][jr]);
            *(float4*)&nxt_r[ao] = vr;
            *(float4*)&nxt_i[ao] = vi;
        }

        float* t;
        t = cur_r; cur_r = nxt_r; nxt_r = t;
        t = cur_i; cur_i = nxt_i; nxt_i = t;
    }
    __syncthreads();

    const float* ur = u_r + (size_t)b * 4096;
    const float* ui = u_i + (size_t)b * 4096;
    float* fb = feat + (size_t)b * 8192;
    for (int e = tid; e < 4096; e += 256) {
        int p = e >> 6, r = e & 63;
        int ao = sw_addr(r, p);
        fb[(p << 7) + r]      = ur[e] - cur_r[ao];
        fb[(p << 7) + 64 + r] = ui[e] - cur_i[ao];
    }
}

// ---------------------------------------------------------------------------
// Phase 2: tensor-core MLP GEMM with bf16x3 error-compensated split.
//   C[512,4096] = mish(A[512,K] @ W[4096,K]^T + bias)
// Tiles 128x128x32, 8 warps (4m x 2n), warp tile 32x64, mma.m16n8k16.bf16.
// smem holds tiles in fragment-major order: each warp-lane's 8 (A) / 4 (B)
// bf16 fragment elements are contiguous -> frag load = 1 LDS.128 / LDS.64.
// ---------------------------------------------------------------------------
__device__ __forceinline__ void mma_m16n8k16(float c[4], const unsigned a[4], const unsigned b[2]) {
    asm volatile(
        "mma.sync.aligned.m16n8k16.row.col.f32.bf16.bf16.f32 "
        "{%0,%1,%2,%3}, {%4,%5,%6,%7}, {%8,%9}, {%0,%1,%2,%3};\n"
        : "+f"(c[0]), "+f"(c[1]), "+f"(c[2]), "+f"(c[3])
        : "r"(a[0]), "r"(a[1]), "r"(a[2]), "r"(a[3]), "r"(b[0]), "r"(b[1]));
}

// padded block strides (elements): A block = 256 frag elems + 8 pad; B = 128 + 8
#define ABLK 264
#define BBLK 136

template <int K>
__global__ void __launch_bounds__(256)
mlp_gemm_tc(const float* __restrict__ A, const float* __restrict__ Bw,
            const float* __restrict__ bias, float* __restrict__ C)
{
    __shared__ __nv_bfloat16 sAh[16 * ABLK], sAl[16 * ABLK];
    __shared__ __nv_bfloat16 sBh[32 * BBLK], sBl[32 * BBLK];

    const int tid = threadIdx.x;
    const int lane = tid & 31, warp = tid >> 5;

    // ---- loader mapping: thread -> (row, k-half) of both tiles
    const int lrow = tid >> 1;        // 0..127
    const int kb2  = tid & 1;         // which k16 half
    const int lk0  = kb2 << 4;

    const float* Ag = A  + (size_t)(blockIdx.y * 128 + lrow) * K + lk0;
    const float* Bg = Bw + (size_t)(blockIdx.x * 128 + lrow) * K + lk0;

    // fragment-store base addresses
    const int rA  = lrow & 15, mbL = lrow >> 4;
    const int aA0 = (mbL * 2 + kb2) * ABLK + (rA & 7) * 32 + ((rA >> 3) << 1);
    const int nbL = lrow >> 3, ncL = lrow & 7;
    const int aB0 = (nbL * 2 + kb2) * BBLK + ncL * 16;

    // per-thread column rotation (bank-conflict spreading) + offsets
    int coA[4], ofA[4], coB[4], ofB[4];
    {
        const int rotA = rA & 3, rotB = ncL & 3;
        #pragma unroll
        for (int j = 0; j < 4; j++) {
            int ii = (j + rotA) & 3;
            coA[j] = ii << 2;
            ofA[j] = ((ii & 1) << 4) | ((ii >> 1) << 2);   // pair 2ii ; +8 for 2ii+1
            ii = (j + rotB) & 3;
            coB[j] = ii << 2;
            ofB[j] = ((ii & 1) << 3) | ((ii >> 1) << 1);   // pair 2ii ; +4 for 2ii+1
        }
    }

    // ---- compute mapping
    const int mb0 = (warp >> 1) * 2;   // A 16-row block base (2 per warp)
    const int nb0 = (warp & 1) * 8;    // B 8-col block base (8 per warp)

    float acc[2][8][4];
    #pragma unroll
    for (int f = 0; f < 2; f++)
        #pragma unroll
        for (int g = 0; g < 8; g++)
            #pragma unroll
            for (int v = 0; v < 4; v++) acc[f][g][v] = 0.f;

    float4 ra[4], rb[4];
    #pragma unroll
    for (int j = 0; j < 4; j++) {
        ra[j] = *(const float4*)&Ag[coA[j]];
        rb[j] = *(const float4*)&Bg[coB[j]];
    }

    #pragma unroll 1
    for (int kb = 0; kb < K; kb += 32) {
        // split fp32 -> bf16 hi/lo and store into fragment-major smem
        #pragma unroll
        for (int j = 0; j < 4; j++) {
            float v0 = ra[j].x, v1 = ra[j].y, v2 = ra[j].z, v3 = ra[j].w;
            __nv_bfloat16 h0 = __float2bfloat16_rn(v0), h1 = __float2bfloat16_rn(v1);
            __nv_bfloat16 h2 = __float2bfloat16_rn(v2), h3 = __float2bfloat16_rn(v3);
            __nv_bfloat162 th0; th0.x = h0; th0.y = h1;
            __nv_bfloat162 th1; th1.x = h2; th1.y = h3;
            __nv_bfloat162 tl0; tl0.x = __float2bfloat16_rn(v0 - __bfloat162float(h0));
                                tl0.y = __float2bfloat16_rn(v1 - __bfloat162float(h1));
            __nv_bfloat162 tl1; tl1.x = __float2bfloat16_rn(v2 - __bfloat162float(h2));
                                tl1.y = __float2bfloat16_rn(v3 - __bfloat162float(h3));
            *(__nv_bfloat162*)&sAh[aA0 + ofA[j]]     = th0;
            *(__nv_bfloat162*)&sAh[aA0 + ofA[j] + 8] = th1;
            *(__nv_bfloat162*)&sAl[aA0 + ofA[j]]     = tl0;
            *(__nv_bfloat162*)&sAl[aA0 + ofA[j] + 8] = tl1;

            v0 = rb[j].x; v1 = rb[j].y; v2 = rb[j].z; v3 = rb[j].w;
            h0 = __float2bfloat16_rn(v0); h1 = __float2bfloat16_rn(v1);
            h2 = __float2bfloat16_rn(v2); h3 = __float2bfloat16_rn(v3);
            __nv_bfloat162 uh0; uh0.x = h0; uh0.y = h1;
            __nv_bfloat162 uh1; uh1.x = h2; uh1.y = h3;
            __nv_bfloat162 ul0; ul0.x = __float2bfloat16_rn(v0 - __bfloat162float(h0));
                                ul0.y = __float2bfloat16_rn(v1 - __bfloat162float(h1));
            __nv_bfloat162 ul1; ul1.x = __float2bfloat16_rn(v2 - __bfloat162float(h2));
                                ul1.y = __float2bfloat16_rn(v3 - __bfloat162float(h3));
            *(__nv_bfloat162*)&sBh[aB0 + ofB[j]]     = uh0;
            *(__nv_bfloat162*)&sBh[aB0 + ofB[j] + 4] = uh1;
            *(__nv_bfloat162*)&sBl[aB0 + ofB[j]]     = ul0;
            *(__nv_bfloat162*)&sBl[aB0 + ofB[j] + 4] = ul1;
        }
        __syncthreads();

        if (kb + 32 < K) {
            #pragma unroll
            for (int j = 0; j < 4; j++) {
                ra[j] = *(const float4*)&Ag[kb + 32 + coA[j]];
                rb[j] = *(const float4*)&Bg[kb + 32 + coB[j]];
            }
        }

        #pragma unroll
        for (int kk = 0; kk < 2; kk++) {
            unsigned ah[2][4], al[2][4];
            #pragma unroll
            for (int f = 0; f < 2; f++) {
                int base = ((mb0 + f) * 2 + kk) * ABLK + lane * 8;
                *(uint4*)ah[f] = *(const uint4*)&sAh[base];
                *(uint4*)al[f] = *(const uint4*)&sAl[base];
            }
            #pragma unroll
            for (int g = 0; g < 8; g++) {
                unsigned bh[2], bl[2];
                int base = ((nb0 + g) * 2 + kk) * BBLK + lane * 4;
                *(uint2*)bh = *(const uint2*)&sBh[base];
                *(uint2*)bl = *(const uint2*)&sBl[base];
                #pragma unroll
                for (int f = 0; f < 2; f++) {
                    mma_m16n8k16(acc[f][g], ah[f], bh);
                    mma_m16n8k16(acc[f][g], ah[f], bl);
                    mma_m16n8k16(acc[f][g], al[f], bh);
                }
            }
        }
        __syncthreads();
    }

    // ---- epilogue: bias + mish, fp32 store
    const int row0  = blockIdx.y * 128 + (warp >> 1) * 32 + (lane >> 2);
    const int col00 = blockIdx.x * 128 + (warp & 1) * 64 + (lane & 3) * 2;
    #pragma unroll
    for (int f = 0; f < 2; f++) {
        #pragma unroll
        for (int g = 0; g < 8; g++) {
            int c = col00 + g * 8;
            float b0 = __ldg(&bias[c]), b1 = __ldg(&bias[c + 1]);
            #pragma unroll
            for (int h = 0; h < 2; h++) {
                int r = row0 + f * 16 + h * 8;
                float2 o;
                o.x = mishf(acc[f][g][2 * h]     + b0);
                o.y = mishf(acc[f][g][2 * h + 1] + b1);
                *(float2*)&C[(size_t)r * 4096 + c] = o;
            }
        }
    }
}

// ---------------------------------------------------------------------------
// Phase 3: out[b] = h2[b,:] . w3 + b3
// ---------------------------------------------------------------------------
__global__ void final_kernel(const float* __restrict__ H,
                             const float* __restrict__ w3,
                             const float* __restrict__ b3,
                             float* __restrict__ out)
{
    const int b = blockIdx.x;
    const float* h = H + (size_t)b * 4096;
    float s = 0.f;
    for (int i = threadIdx.x; i < 4096; i += 256)
        s = fmaf(h[i], w3[i], s);
    #pragma unroll
    for (int o = 16; o > 0; o >>= 1)
        s += __shfl_down_sync(0xffffffffu, s, o);
    __shared__ float red[8];
    if ((threadIdx.x & 31) == 0) red[threadIdx.x >> 5] = s;
    __syncthreads();
    if (threadIdx.x == 0) {
        float t = 0.f;
        #pragma unroll
        for (int i = 0; i < 8; i++) t += red[i];
        out[b] = t + b3[0];
    }
}

// ---------------------------------------------------------------------------
extern "C" void kernel_launch(void* const* d_in, const int* in_sizes, int n_in,
                              void* d_out, int out_size)
{
    const float* x_r = (const float*)d_in[0];
    const float* x_i = (const float*)d_in[1];
    const float* u_r = (const float*)d_in[2];
    const float* u_i = (const float*)d_in[3];
    const float* W_r = (const float*)d_in[4];
    const float* W_i = (const float*)d_in[5];
    const float* w1  = (const float*)d_in[6];
    const float* b1  = (const float*)d_in[7];
    const float* w2  = (const float*)d_in[8];
    const float* b2  = (const float*)d_in[9];
    const float* w3  = (const float*)d_in[10];
    const float* b3  = (const float*)d_in[11];
    float* out = (float*)d_out;

    float *feat, *h1, *h2;
    cudaGetSymbolAddress((void**)&feat, g_feat);
    cudaGetSymbolAddress((void**)&h1, g_h1);
    cudaGetSymbolAddress((void**)&h2, g_h2);

    cudaFuncSetAttribute((const void*)chain_kernel,
                         cudaFuncAttributeMaxDynamicSharedMemorySize, 98304);

    chain_kernel<<<512, dim3(16, 16), 98304>>>(x_r, x_i, u_r, u_i, W_r, W_i, feat);
    mlp_gemm_tc<8192><<<dim3(32, 4), 256>>>(feat, w1, b1, h1);
    mlp_gemm_tc<4096><<<dim3(32, 4), 256>>>(h1, w2, b2, h2);
    final_kernel<<<512, 256>>>(h2, w3, b3, out);
}

// round 3
// speedup vs baseline: 3.8786x; 1.3528x over previous
#include <cuda_runtime.h>
#include <cuda_bf16.h>
#include <math.h>

// ---------------- scratch (device globals: allocation-free rule) -------------
__device__ float g_feat[512 * 8192];   // chain output features
__device__ float g_h1[512 * 4096];     // MLP hidden 1
__device__ float g_h2[512 * 4096];     // MLP hidden 2

__device__ __forceinline__ float mishf(float x) {
    float sp = (x > 20.f) ? x : log1pf(expf(x));
    return x * tanhf(sp);
}

__device__ __forceinline__ void mma_m16n8k16(float c[4], const unsigned a[4], const unsigned b[2]) {
    asm volatile(
        "mma.sync.aligned.m16n8k16.row.col.f32.bf16.bf16.f32 "
        "{%0,%1,%2,%3}, {%4,%5,%6,%7}, {%8,%9}, {%0,%1,%2,%3};\n"
        : "+f"(c[0]), "+f"(c[1]), "+f"(c[2]), "+f"(c[3])
        : "r"(a[0]), "r"(a[1]), "r"(a[2]), "r"(a[3]), "r"(b[0]), "r"(b[1]));
}

__device__ __forceinline__ void split2(float v, __nv_bfloat16& h, __nv_bfloat16& l) {
    h = __float2bfloat16_rn(v);
    l = __float2bfloat16_rn(v - __bfloat162float(h));
}

// ---------------------------------------------------------------------------
// Phase 1: complex matrix chain on tensor cores (bf16x3 split).
// One CTA (256 thr, 8 warps) per batch. 15 sequential complex 64x64 matmuls.
//
// smem (bf16, 64KB dynamic):
//   A operand (M = W or x), A-frag-major: sMrh,sMrl,sMih,sMil  (4096 bf16 each)
//   B operand (running cur), B-frag-major: sCrh,sCrl,sCih,sCil (4096 bf16 each)
//
// A-frag-major: 16 blocks (mb0..3 x kb0..3), block = 32 lanes * 8 bf16
//   lane holds a0(R,K0|K0+1) a1(R+8,..) a2(R,K0+8|9) a3(R+8,K0+8|9)
// B-frag-major: 32 blocks (nb0..7 x kb0..3), block = 32 lanes * 4 bf16
//   lane holds b0(K0|K0+1, n) b1(K0+8|9, n); element value = cur[k][n]
// ---------------------------------------------------------------------------
__global__ void __launch_bounds__(256)
chain_tc(const float* __restrict__ x_r, const float* __restrict__ x_i,
         const float* __restrict__ u_r, const float* __restrict__ u_i,
         const float* __restrict__ W_r, const float* __restrict__ W_i,
         float* __restrict__ feat)
{
    extern __shared__ __nv_bfloat16 sm[];
    __nv_bfloat16* sMrh = sm;
    __nv_bfloat16* sMrl = sm + 4096;
    __nv_bfloat16* sMih = sm + 8192;
    __nv_bfloat16* sMil = sm + 12288;
    __nv_bfloat16* sCrh = sm + 16384;
    __nv_bfloat16* sCrl = sm + 20480;
    __nv_bfloat16* sCih = sm + 24576;
    __nv_bfloat16* sCil = sm + 28672;

    const int tid = threadIdx.x;
    const int lane = tid & 31, warp = tid >> 5;
    const int b = blockIdx.x;

    const float* xr = x_r + (size_t)b * 8 * 4096;
    const float* xi = x_i + (size_t)b * 8 * 4096;

    // ---- init: split x[b,0] into C bufs (B-frag-major). cur[k][n] = x0[k][n]
    #pragma unroll
    for (int j = 0; j < 4; j++) {
        int bi = warp + 8 * j;             // 0..31
        int nb = bi >> 2, kb = bi & 3;
        int n  = nb * 8 + (lane >> 2);
        int k0 = kb * 16 + 2 * (lane & 3);
        int base = bi * 128 + lane * 4;
        float v0 = xr[k0 * 64 + n];
        float v1 = xr[(k0 + 1) * 64 + n];
        float v2 = xr[(k0 + 8) * 64 + n];
        float v3 = xr[(k0 + 9) * 64 + n];
        __nv_bfloat16 h, l;
        split2(v0, h, l); sCrh[base]     = h; sCrl[base]     = l;
        split2(v1, h, l); sCrh[base + 1] = h; sCrl[base + 1] = l;
        split2(v2, h, l); sCrh[base + 2] = h; sCrl[base + 2] = l;
        split2(v3, h, l); sCrh[base + 3] = h; sCrl[base + 3] = l;
        v0 = xi[k0 * 64 + n];
        v1 = xi[(k0 + 1) * 64 + n];
        v2 = xi[(k0 + 8) * 64 + n];
        v3 = xi[(k0 + 9) * 64 + n];
        split2(v0, h, l); sCih[base]     = h; sCil[base]     = l;
        split2(v1, h, l); sCih[base + 1] = h; sCil[base + 1] = l;
        split2(v2, h, l); sCih[base + 2] = h; sCil[base + 2] = l;
        split2(v3, h, l); sCih[base + 3] = h; sCil[base + 3] = l;
    }

    const int mb  = warp >> 1;           // A 16-row block for this warp
    const int nb0 = (warp & 1) * 4;      // first of 4 B n-blocks

    float aDr1[4][4], aDr2[4][4], aDi[4][4];

    #pragma unroll 1
    for (int s = 0; s < 15; s++) {
        const float* Mr;
        const float* Mi;
        if (s & 1) { int l = (s + 1) >> 1; Mr = xr  + l * 4096; Mi = xi  + l * 4096; }
        else       { int l = s >> 1;       Mr = W_r + l * 4096; Mi = W_i + l * 4096; }

        // ---- split M into A bufs (A-frag-major); blocks warp, warp+8
        #pragma unroll
        for (int j = 0; j < 2; j++) {
            int bi = warp + 8 * j;           // 0..15
            int mbl = bi >> 2, kbl = bi & 3;
            int R  = mbl * 16 + (lane >> 2);
            int K0 = kbl * 16 + 2 * (lane & 3);
            int base = bi * 256 + lane * 8;
            float2 p0 = *(const float2*)&Mr[R * 64 + K0];
            float2 p1 = *(const float2*)&Mr[(R + 8) * 64 + K0];
            float2 p2 = *(const float2*)&Mr[R * 64 + K0 + 8];
            float2 p3 = *(const float2*)&Mr[(R + 8) * 64 + K0 + 8];
            __nv_bfloat16 h, l;
            split2(p0.x, h, l); sMrh[base]     = h; sMrl[base]     = l;
            split2(p0.y, h, l); sMrh[base + 1] = h; sMrl[base + 1] = l;
            split2(p1.x, h, l); sMrh[base + 2] = h; sMrl[base + 2] = l;
            split2(p1.y, h, l); sMrh[base + 3] = h; sMrl[base + 3] = l;
            split2(p2.x, h, l); sMrh[base + 4] = h; sMrl[base + 4] = l;
            split2(p2.y, h, l); sMrh[base + 5] = h; sMrl[base + 5] = l;
            split2(p3.x, h, l); sMrh[base + 6] = h; sMrl[base + 6] = l;
            split2(p3.y, h, l); sMrh[base + 7] = h; sMrl[base + 7] = l;
            p0 = *(const float2*)&Mi[R * 64 + K0];
            p1 = *(const float2*)&Mi[(R + 8) * 64 + K0];
            p2 = *(const float2*)&Mi[R * 64 + K0 + 8];
            p3 = *(const float2*)&Mi[(R + 8) * 64 + K0 + 8];
            split2(p0.x, h, l); sMih[base]     = h; sMil[base]     = l;
            split2(p0.y, h, l); sMih[base + 1] = h; sMil[base + 1] = l;
            split2(p1.x, h, l); sMih[base + 2] = h; sMil[base + 2] = l;
            split2(p1.y, h, l); sMih[base + 3] = h; sMil[base + 3] = l;
            split2(p2.x, h, l); sMih[base + 4] = h; sMil[base + 4] = l;
            split2(p2.y, h, l); sMih[base + 5] = h; sMil[base + 5] = l;
            split2(p3.x, h, l); sMih[base + 6] = h; sMil[base + 6] = l;
            split2(p3.y, h, l); sMih[base + 7] = h; sMil[base + 7] = l;
        }
        __syncthreads();   // A + C stores visible

        // ---- mma: Dr1 = Mr*Cr, Dr2 = Mi*Ci, Di = Mr*Ci + Mi*Cr (each bf16x3)
        #pragma unroll
        for (int g = 0; g < 4; g++)
            #pragma unroll
            for (int v = 0; v < 4; v++) { aDr1[g][v] = 0.f; aDr2[g][v] = 0.f; aDi[g][v] = 0.f; }

        #pragma unroll
        for (int kb = 0; kb < 4; kb++) {
            unsigned arh[4], arl[4], aih[4], ail[4];
            int abase = (mb * 4 + kb) * 256 + lane * 8;
            *(uint4*)arh = *(const uint4*)&sMrh[abase];
            *(uint4*)arl = *(const uint4*)&sMrl[abase];
            *(uint4*)aih = *(const uint4*)&sMih[abase];
            *(uint4*)ail = *(const uint4*)&sMil[abase];
            #pragma unroll
            for (int g = 0; g < 4; g++) {
                unsigned brh[2], brl[2], bih[2], bil[2];
                int bbase = ((nb0 + g) * 4 + kb) * 128 + lane * 4;
                *(uint2*)brh = *(const uint2*)&sCrh[bbase];
                *(uint2*)brl = *(const uint2*)&sCrl[bbase];
                *(uint2*)bih = *(const uint2*)&sCih[bbase];
                *(uint2*)bil = *(const uint2*)&sCil[bbase];
                mma_m16n8k16(aDr1[g], arh, brh);
                mma_m16n8k16(aDr1[g], arh, brl);
                mma_m16n8k16(aDr1[g], arl, brh);
                mma_m16n8k16(aDr2[g], aih, bih);
                mma_m16n8k16(aDr2[g], aih, bil);
                mma_m16n8k16(aDr2[g], ail, bih);
                mma_m16n8k16(aDi[g],  arh, bih);
                mma_m16n8k16(aDi[g],  arh, bil);
                mma_m16n8k16(aDi[g],  arl, bih);
                mma_m16n8k16(aDi[g],  aih, brh);
                mma_m16n8k16(aDi[g],  aih, brl);
                mma_m16n8k16(aDi[g],  ail, brh);
            }
        }
        __syncthreads();   // all C reads done before overwrite below

        if (s < 14) {
            // ---- scatter D back into C bufs (B-frag-major for next step)
            // D element (p, r): p = mb*16 + lane/4 + 8*(ci>>1),
            //                   r = (nb0+g)*8 + 2*(lane&3) + (ci&1)
            #pragma unroll
            for (int g = 0; g < 4; g++) {
                int rbase = (nb0 + g) * 8 + 2 * (lane & 3);
                #pragma unroll
                for (int ci = 0; ci < 4; ci++) {
                    int p = mb * 16 + (lane >> 2) + 8 * (ci >> 1);
                    int r = rbase + (ci & 1);
                    int nbp = r >> 3, kbp = p >> 4;
                    int lp = 4 * (r & 7) + ((p & 7) >> 1);
                    int addr = (nbp * 4 + kbp) * 128 + lp * 4 + (((p & 15) >= 8) ? 2 : 0) + (p & 1);
                    float vr = aDr1[g][ci] - aDr2[g][ci];
                    float vi = aDi[g][ci];
                    __nv_bfloat16 h, l;
                    split2(vr, h, l); sCrh[addr] = h; sCrl[addr] = l;
                    split2(vi, h, l); sCih[addr] = h; sCil[addr] = l;
                }
            }
        }
    }

    // ---- epilogue: feat[b, p*128 + r] = u_r - Dr ; +64: u_i - Di
    const float* ur = u_r + (size_t)b * 4096;
    const float* ui = u_i + (size_t)b * 4096;
    float* fb = feat + (size_t)b * 8192;
    #pragma unroll
    for (int g = 0; g < 4; g++) {
        int r = (nb0 + g) * 8 + 2 * (lane & 3);
        #pragma unroll
        for (int h = 0; h < 2; h++) {
            int p = mb * 16 + (lane >> 2) + 8 * h;
            float2 u2 = *(const float2*)&ur[p * 64 + r];
            float2 o;
            o.x = u2.x - (aDr1[g][2 * h]     - aDr2[g][2 * h]);
            o.y = u2.y - (aDr1[g][2 * h + 1] - aDr2[g][2 * h + 1]);
            *(float2*)&fb[(p << 7) + r] = o;
            u2 = *(const float2*)&ui[p * 64 + r];
            o.x = u2.x - aDi[g][2 * h];
            o.y = u2.y - aDi[g][2 * h + 1];
            *(float2*)&fb[(p << 7) + 64 + r] = o;
        }
    }
}

// ---------------------------------------------------------------------------
// Phase 2: tensor-core MLP GEMM with bf16x3 split (unchanged from R2).
// ---------------------------------------------------------------------------
#define ABLK 264
#define BBLK 136

template <int K>
__global__ void __launch_bounds__(256)
mlp_gemm_tc(const float* __restrict__ A, const float* __restrict__ Bw,
            const float* __restrict__ bias, float* __restrict__ C)
{
    __shared__ __nv_bfloat16 sAh[16 * ABLK], sAl[16 * ABLK];
    __shared__ __nv_bfloat16 sBh[32 * BBLK], sBl[32 * BBLK];

    const int tid = threadIdx.x;
    const int lane = tid & 31, warp = tid >> 5;

    const int lrow = tid >> 1;
    const int kb2  = tid & 1;
    const int lk0  = kb2 << 4;

    const float* Ag = A  + (size_t)(blockIdx.y * 128 + lrow) * K + lk0;
    const float* Bg = Bw + (size_t)(blockIdx.x * 128 + lrow) * K + lk0;

    const int rA  = lrow & 15, mbL = lrow >> 4;
    const int aA0 = (mbL * 2 + kb2) * ABLK + (rA & 7) * 32 + ((rA >> 3) << 1);
    const int nbL = lrow >> 3, ncL = lrow & 7;
    const int aB0 = (nbL * 2 + kb2) * BBLK + ncL * 16;

    int coA[4], ofA[4], coB[4], ofB[4];
    {
        const int rotA = rA & 3, rotB = ncL & 3;
        #pragma unroll
        for (int j = 0; j < 4; j++) {
            int ii = (j + rotA) & 3;
            coA[j] = ii << 2;
            ofA[j] = ((ii & 1) << 4) | ((ii >> 1) << 2);
            ii = (j + rotB) & 3;
            coB[j] = ii << 2;
            ofB[j] = ((ii & 1) << 3) | ((ii >> 1) << 1);
        }
    }

    const int mb0 = (warp >> 1) * 2;
    const int nb0 = (warp & 1) * 8;

    float acc[2][8][4];
    #pragma unroll
    for (int f = 0; f < 2; f++)
        #pragma unroll
        for (int g = 0; g < 8; g++)
            #pragma unroll
            for (int v = 0; v < 4; v++) acc[f][g][v] = 0.f;

    float4 ra[4], rb[4];
    #pragma unroll
    for (int j = 0; j < 4; j++) {
        ra[j] = *(const float4*)&Ag[coA[j]];
        rb[j] = *(const float4*)&Bg[coB[j]];
    }

    #pragma unroll 1
    for (int kb = 0; kb < K; kb += 32) {
        #pragma unroll
        for (int j = 0; j < 4; j++) {
            float v0 = ra[j].x, v1 = ra[j].y, v2 = ra[j].z, v3 = ra[j].w;
            __nv_bfloat16 h0, h1, h2, h3, l0, l1, l2, l3;
            split2(v0, h0, l0); split2(v1, h1, l1); split2(v2, h2, l2); split2(v3, h3, l3);
            __nv_bfloat162 th0; th0.x = h0; th0.y = h1;
            __nv_bfloat162 th1; th1.x = h2; th1.y = h3;
            __nv_bfloat162 tl0; tl0.x = l0; tl0.y = l1;
            __nv_bfloat162 tl1; tl1.x = l2; tl1.y = l3;
            *(__nv_bfloat162*)&sAh[aA0 + ofA[j]]     = th0;
            *(__nv_bfloat162*)&sAh[aA0 + ofA[j] + 8] = th1;
            *(__nv_bfloat162*)&sAl[aA0 + ofA[j]]     = tl0;
            *(__nv_bfloat162*)&sAl[aA0 + ofA[j] + 8] = tl1;

            v0 = rb[j].x; v1 = rb[j].y; v2 = rb[j].z; v3 = rb[j].w;
            split2(v0, h0, l0); split2(v1, h1, l1); split2(v2, h2, l2); split2(v3, h3, l3);
            __nv_bfloat162 uh0; uh0.x = h0; uh0.y = h1;
            __nv_bfloat162 uh1; uh1.x = h2; uh1.y = h3;
            __nv_bfloat162 ul0; ul0.x = l0; ul0.y = l1;
            __nv_bfloat162 ul1; ul1.x = l2; ul1.y = l3;
            *(__nv_bfloat162*)&sBh[aB0 + ofB[j]]     = uh0;
            *(__nv_bfloat162*)&sBh[aB0 + ofB[j] + 4] = uh1;
            *(__nv_bfloat162*)&sBl[aB0 + ofB[j]]     = ul0;
            *(__nv_bfloat162*)&sBl[aB0 + ofB[j] + 4] = ul1;
        }
        __syncthreads();

        if (kb + 32 < K) {
            #pragma unroll
            for (int j = 0; j < 4; j++) {
                ra[j] = *(const float4*)&Ag[kb + 32 + coA[j]];
                rb[j] = *(const float4*)&Bg[kb + 32 + coB[j]];
            }
        }

        #pragma unroll
        for (int kk = 0; kk < 2; kk++) {
            unsigned ah[2][4], al[2][4];
            #pragma unroll
            for (int f = 0; f < 2; f++) {
                int base = ((mb0 + f) * 2 + kk) * ABLK + lane * 8;
                *(uint4*)ah[f] = *(const uint4*)&sAh[base];
                *(uint4*)al[f] = *(const uint4*)&sAl[base];
            }
            #pragma unroll
            for (int g = 0; g < 8; g++) {
                unsigned bh[2], bl[2];
                int base = ((nb0 + g) * 2 + kk) * BBLK + lane * 4;
                *(uint2*)bh = *(const uint2*)&sBh[base];
                *(uint2*)bl = *(const uint2*)&sBl[base];
                #pragma unroll
                for (int f = 0; f < 2; f++) {
                    mma_m16n8k16(acc[f][g], ah[f], bh);
                    mma_m16n8k16(acc[f][g], ah[f], bl);
                    mma_m16n8k16(acc[f][g], al[f], bh);
                }
            }
        }
        __syncthreads();
    }

    const int row0  = blockIdx.y * 128 + (warp >> 1) * 32 + (lane >> 2);
    const int col00 = blockIdx.x * 128 + (warp & 1) * 64 + (lane & 3) * 2;
    #pragma unroll
    for (int f = 0; f < 2; f++) {
        #pragma unroll
        for (int g = 0; g < 8; g++) {
            int c = col00 + g * 8;
            float b0 = __ldg(&bias[c]), b1 = __ldg(&bias[c + 1]);
            #pragma unroll
            for (int h = 0; h < 2; h++) {
                int r = row0 + f * 16 + h * 8;
                float2 o;
                o.x = mishf(acc[f][g][2 * h]     + b0);
                o.y = mishf(acc[f][g][2 * h + 1] + b1);
                *(float2*)&C[(size_t)r * 4096 + c] = o;
            }
        }
    }
}

// ---------------------------------------------------------------------------
// Phase 3: out[b] = h2[b,:] . w3 + b3
// ---------------------------------------------------------------------------
__global__ void final_kernel(const float* __restrict__ H,
                             const float* __restrict__ w3,
                             const float* __restrict__ b3,
                             float* __restrict__ out)
{
    const int b = blockIdx.x;
    const float* h = H + (size_t)b * 4096;
    float s = 0.f;
    for (int i = threadIdx.x; i < 4096; i += 256)
        s = fmaf(h[i], w3[i], s);
    #pragma unroll
    for (int o = 16; o > 0; o >>= 1)
        s += __shfl_down_sync(0xffffffffu, s, o);
    __shared__ float red[8];
    if ((threadIdx.x & 31) == 0) red[threadIdx.x >> 5] = s;
    __syncthreads();
    if (threadIdx.x == 0) {
        float t = 0.f;
        #pragma unroll
        for (int i = 0; i < 8; i++) t += red[i];
        out[b] = t + b3[0];
    }
}

// ---------------------------------------------------------------------------
extern "C" void kernel_launch(void* const* d_in, const int* in_sizes, int n_in,
                              void* d_out, int out_size)
{
    const float* x_r = (const float*)d_in[0];
    const float* x_i = (const float*)d_in[1];
    const float* u_r = (const float*)d_in[2];
    const float* u_i = (const float*)d_in[3];
    const float* W_r = (const float*)d_in[4];
    const float* W_i = (const float*)d_in[5];
    const float* w1  = (const float*)d_in[6];
    const float* b1  = (const float*)d_in[7];
    const float* w2  = (const float*)d_in[8];
    const float* b2  = (const float*)d_in[9];
    const float* w3  = (const float*)d_in[10];
    const float* b3  = (const float*)d_in[11];
    float* out = (float*)d_out;

    float *feat, *h1, *h2;
    cudaGetSymbolAddress((void**)&feat, g_feat);
    cudaGetSymbolAddress((void**)&h1, g_h1);
    cudaGetSymbolAddress((void**)&h2, g_h2);

    cudaFuncSetAttribute((const void*)chain_tc,
                         cudaFuncAttributeMaxDynamicSharedMemorySize, 65536);

    chain_tc<<<512, 256, 65536>>>(x_r, x_i, u_r, u_i, W_r, W_i, feat);
    mlp_gemm_tc<8192><<<dim3(32, 4), 256>>>(feat, w1, b1, h1);
    mlp_gemm_tc<4096><<<dim3(32, 4), 256>>>(h1, w2, b2, h2);
    final_kernel<<<512, 256>>>(h2, w3, b3, out);
}